// round 6
// baseline (speedup 1.0000x reference)
#include <cuda_runtime.h>
#include <cstdint>

// MixtureLowRankRNN — GB300 sm_103a.
// Subspace identity: h_t ∈ colspan([m|I]) (h0=0) ⇒ outputs are basis coords:
//   y[:,t,0:4]  = a_s*S_{t+1},  S <- 0.9 S + u_t,  u_t = n^T tanh(h_t)
//   y[:,t,4:20] = 0.1*X_{t+1},  X <- 0.9 X + x_t
// Round 6: hoist all input-only work out of the serial loop.
//   kernel 1 (z_kernel):  Z[b,t,h] = 0.1 * (I @ x_t)[h], thread-permuted layout
//   kernel 2 (xscan):     writes y[:,:,4:20] directly (pure x scan)
//   kernel 3 (rnn):       serial recurrence; per step only tanh+dot+reduce+
//                         1 LDG.128 (prefetched Z) + corrections.

#define RANKN 4
#define INPN  16
#define TLEN  1024
#define BATCH 32
#define NTHR  256
#define TCH   16    // t-chunks per batch in z_kernel

typedef unsigned long long u64;

// 128 MB device scratch: Z[(b*TLEN + t)*256 + tid] = float4 of this thread's
// 4 h-elements {tid, tid+256, tid+512, tid+768}, pre-scaled by 0.1.
__device__ ulonglong2 g_z[BATCH * TLEN * 256];

__device__ __forceinline__ u64 pack2(float x, float y) {
    u64 r; asm("mov.b64 %0, {%1, %2};" : "=l"(r) : "f"(x), "f"(y)); return r;
}
__device__ __forceinline__ void unpack2(u64 v, float& x, float& y) {
    asm("mov.b64 {%0, %1}, %2;" : "=f"(x), "=f"(y) : "l"(v));
}
__device__ __forceinline__ u64 fma2(u64 a, u64 b, u64 c) {
    u64 d; asm("fma.rn.f32x2 %0, %1, %2, %3;" : "=l"(d) : "l"(a), "l"(b), "l"(c)); return d;
}
__device__ __forceinline__ u64 mul2(u64 a, u64 b) {
    u64 d; asm("mul.rn.f32x2 %0, %1, %2;" : "=l"(d) : "l"(a), "l"(b)); return d;
}
__device__ __forceinline__ u64 add2(u64 a, u64 b) {
    u64 d; asm("add.rn.f32x2 %0, %1, %2;" : "=l"(d) : "l"(a), "l"(b)); return d;
}
__device__ __forceinline__ float tanha(float x) {
    float r; asm("tanh.approx.f32 %0, %1;" : "=f"(r) : "f"(x)); return r;
}

// 6-shfl transposed warp reduce: returns warp-sum of p_{lane&3}.
__device__ __forceinline__ float warp_reduce4(float p0, float p1, float p2, float p3, int lane) {
    const bool b0 = lane & 1;
    const bool b1 = lane & 2;
    float sA = b0 ? p0 : p1;
    float rA = __shfl_xor_sync(0xffffffffu, sA, 1);
    float q0 = (b0 ? p1 : p0) + rA;
    float sB = b0 ? p2 : p3;
    float rB = __shfl_xor_sync(0xffffffffu, sB, 1);
    float q1 = (b0 ? p3 : p2) + rB;
    float sC = b1 ? q0 : q1;
    float rC = __shfl_xor_sync(0xffffffffu, sC, 2);
    float w  = (b1 ? q1 : q0) + rC;
    w += __shfl_xor_sync(0xffffffffu, w, 4);
    w += __shfl_xor_sync(0xffffffffu, w, 8);
    w += __shfl_xor_sync(0xffffffffu, w, 16);
    return w;
}

// ============ kernel 1: Z = 0.1 * x @ I^T, permuted layout ============
__global__ __launch_bounds__(NTHR)
void z_kernel(const float* __restrict__ x, const float* __restrict__ I) {
    const int b   = blockIdx.x / TCH;
    const int tc  = blockIdx.x % TCH;
    const int tid = threadIdx.x;
    const int eA0 = tid,       eA1 = tid + 256;
    const int eB0 = tid + 512, eB1 = tid + 768;

    u64 Ia[INPN], Ib[INPN];
#pragma unroll
    for (int j = 0; j < INPN; j++) {
        Ia[j] = pack2(0.1f * I[eA0 * INPN + j], 0.1f * I[eA1 * INPN + j]);
        Ib[j] = pack2(0.1f * I[eB0 * INPN + j], 0.1f * I[eB1 * INPN + j]);
    }
    const float* xb = x + (size_t)b * TLEN * INPN;
    const int t0 = tc * (TLEN / TCH), t1 = t0 + (TLEN / TCH);

    for (int t = t0; t < t1; t++) {
        const float4* xr = (const float4*)(xb + (size_t)t * INPN);
        float4 f0 = xr[0], f1 = xr[1], f2 = xr[2], f3 = xr[3];
        u64 xd[INPN];
        xd[0]=pack2(f0.x,f0.x); xd[1]=pack2(f0.y,f0.y); xd[2]=pack2(f0.z,f0.z); xd[3]=pack2(f0.w,f0.w);
        xd[4]=pack2(f1.x,f1.x); xd[5]=pack2(f1.y,f1.y); xd[6]=pack2(f1.z,f1.z); xd[7]=pack2(f1.w,f1.w);
        xd[8]=pack2(f2.x,f2.x); xd[9]=pack2(f2.y,f2.y); xd[10]=pack2(f2.z,f2.z); xd[11]=pack2(f2.w,f2.w);
        xd[12]=pack2(f3.x,f3.x); xd[13]=pack2(f3.y,f3.y); xd[14]=pack2(f3.z,f3.z); xd[15]=pack2(f3.w,f3.w);

        u64 aA0 = fma2(Ia[4],  xd[4],  mul2(Ia[0], xd[0]));
        u64 aB0 = fma2(Ib[4],  xd[4],  mul2(Ib[0], xd[0]));
        u64 aA1 = fma2(Ia[5],  xd[5],  mul2(Ia[1], xd[1]));
        u64 aB1 = fma2(Ib[5],  xd[5],  mul2(Ib[1], xd[1]));
        u64 aA2 = fma2(Ia[6],  xd[6],  mul2(Ia[2], xd[2]));
        u64 aB2 = fma2(Ib[6],  xd[6],  mul2(Ib[2], xd[2]));
        u64 aA3 = fma2(Ia[7],  xd[7],  mul2(Ia[3], xd[3]));
        u64 aB3 = fma2(Ib[7],  xd[7],  mul2(Ib[3], xd[3]));
        aA0 = fma2(Ia[8],  xd[8],  aA0);  aB0 = fma2(Ib[8],  xd[8],  aB0);
        aA1 = fma2(Ia[9],  xd[9],  aA1);  aB1 = fma2(Ib[9],  xd[9],  aB1);
        aA2 = fma2(Ia[10], xd[10], aA2);  aB2 = fma2(Ib[10], xd[10], aB2);
        aA3 = fma2(Ia[11], xd[11], aA3);  aB3 = fma2(Ib[11], xd[11], aB3);
        aA0 = fma2(Ia[12], xd[12], aA0);  aB0 = fma2(Ib[12], xd[12], aB0);
        aA1 = fma2(Ia[13], xd[13], aA1);  aB1 = fma2(Ib[13], xd[13], aB1);
        aA2 = fma2(Ia[14], xd[14], aA2);  aB2 = fma2(Ib[14], xd[14], aB2);
        aA3 = fma2(Ia[15], xd[15], aA3);  aB3 = fma2(Ib[15], xd[15], aB3);
        u64 zA = add2(add2(aA0, aA1), add2(aA2, aA3));
        u64 zB = add2(add2(aB0, aB1), add2(aB2, aB3));

        ulonglong2 zo; zo.x = zA; zo.y = zB;
        g_z[((size_t)b * TLEN + t) * 256 + tid] = zo;
    }
}

// ============ kernel 2: y[:,:,4:20] = 0.1 * decayed x scan ============
__global__ void xscan_kernel(const float* __restrict__ x, float* __restrict__ out) {
    const int b = blockIdx.x;
    const int j = threadIdx.x;       // 0..15
    const float* xb = x   + (size_t)b * TLEN * INPN + j;
    float*       ob = out + (size_t)b * TLEN * 20 + 4 + j;
    float X = 0.f;
#pragma unroll 8
    for (int t = 0; t < TLEN; t++) {
        X = fmaf(0.9f, X, xb[(size_t)t * INPN]);
        ob[(size_t)t * 20] = 0.1f * X;
    }
}

// ============ kernel 3: the serial recurrence ============
__global__ __launch_bounds__(NTHR, 1)
void rnn_kernel(const float* __restrict__ m,
                const float* __restrict__ n,
                float* __restrict__ out)       // [B, T, 20]
{
    const int b    = blockIdx.x;
    const int tid  = threadIdx.x;
    const int wid  = tid >> 5;
    const int lane = tid & 31;

    __shared__ float4 s_part[2][8];   // [buf][warp] partial {u0..u3}

    const float a_s = 0.1f * (500.0f / 1024.0f);
    const int eA0 = tid,       eA1 = tid + 256;
    const int eB0 = tid + 512, eB1 = tid + 768;

    u64 na[RANKN], nb[RANKN], mcA[RANKN], mcB[RANKN];
#pragma unroll
    for (int r = 0; r < RANKN; r++) {
        na[r]  = pack2(n[eA0 * RANKN + r], n[eA1 * RANKN + r]);
        nb[r]  = pack2(n[eB0 * RANKN + r], n[eB1 * RANKN + r]);
        mcA[r] = pack2(a_s * m[eA0 * RANKN + r], a_s * m[eA1 * RANKN + r]);
        mcB[r] = pack2(a_s * m[eB0 * RANKN + r], a_s * m[eB1 * RANKN + r]);
    }

    const u64 c9  = pack2(0.9f, 0.9f);
    const u64 asd = pack2(a_s, a_s);

    float* outb = out + (size_t)b * TLEN * 20;
    const ulonglong2* zp = g_z + (size_t)b * TLEN * 256 + tid;

    u64 hA = 0ull, hB = 0ull;
    u64 S01 = 0ull, S23 = 0ull;      // warp0 lane0

    ulonglong2 zcur = zp[0];          // Z for t=0

    for (int t = 0; t < TLEN; t++) {
        // ---- prefetch Z_{t+1} (coalesced LDG.128, spans the whole step) ----
        const size_t tn = (t + 1 < TLEN) ? (size_t)(t + 1) : (size_t)t;
        ulonglong2 znext = zp[tn * 256];

        // ---- critical path: tanh(h), low-rank dot, warp reduce ----
        float a0, a1, b0v, b1v;
        unpack2(hA, a0, a1); unpack2(hB, b0v, b1v);
        u64 thA = pack2(tanha(a0), tanha(a1));
        u64 thB = pack2(tanha(b0v), tanha(b1v));

        float p[4];
#pragma unroll
        for (int r = 0; r < RANKN; r++) {
            float lo, hi; unpack2(fma2(na[r], thA, mul2(nb[r], thB)), lo, hi);
            p[r] = lo + hi;
        }
        float w = warp_reduce4(p[0], p[1], p[2], p[3], lane);
        if (lane < 4) ((float*)&s_part[t & 1][wid])[lane] = w;

        // ---- u-independent part: acc = 0.9 h + Z_t (one fma2 per pair) ----
        u64 accA = fma2(c9, hA, zcur.x);
        u64 accB = fma2(c9, hB, zcur.y);

        __syncthreads();   // the only barrier per step

        // ---- cross-warp combine (broadcast LDS.128 + f32x2 tree) ----
        const float4* sp = s_part[t & 1];
        ulonglong2 v0 = *(const ulonglong2*)&sp[0];
        ulonglong2 v1 = *(const ulonglong2*)&sp[1];
        ulonglong2 v2 = *(const ulonglong2*)&sp[2];
        ulonglong2 v3 = *(const ulonglong2*)&sp[3];
        ulonglong2 v4 = *(const ulonglong2*)&sp[4];
        ulonglong2 v5 = *(const ulonglong2*)&sp[5];
        ulonglong2 v6 = *(const ulonglong2*)&sp[6];
        ulonglong2 v7 = *(const ulonglong2*)&sp[7];
        u64 U01 = add2(add2(add2(v0.x, v1.x), add2(v2.x, v3.x)),
                       add2(add2(v4.x, v5.x), add2(v6.x, v7.x)));
        u64 U23 = add2(add2(add2(v0.y, v1.y), add2(v2.y, v3.y)),
                       add2(add2(v4.y, v5.y), add2(v6.y, v7.y)));

        float q0, q1, q2, q3;
        unpack2(U01, q0, q1); unpack2(U23, q2, q3);
        u64 U0d = pack2(q0, q0), U1d = pack2(q1, q1);
        u64 U2d = pack2(q2, q2), U3d = pack2(q3, q3);

        // h_{t+1} = acc + sum_r (a_s m_r) u_r
        u64 cA0 = fma2(mcA[1], U1d, mul2(mcA[0], U0d));
        u64 cB0 = fma2(mcB[1], U1d, mul2(mcB[0], U0d));
        u64 cA1 = fma2(mcA[3], U3d, mul2(mcA[2], U2d));
        u64 cB1 = fma2(mcB[3], U3d, mul2(mcB[2], U2d));
        hA = add2(accA, add2(cA0, cA1));
        hB = add2(accB, add2(cB0, cB1));

        // ---- low-rank coordinate output (off critical path) ----
        if (wid == 0 && lane == 0) {
            S01 = fma2(c9, S01, U01);
            S23 = fma2(c9, S23, U23);
            float o0, o1, o2, o3;
            unpack2(mul2(asd, S01), o0, o1);
            unpack2(mul2(asd, S23), o2, o3);
            *(float4*)(outb + (size_t)t * 20) = make_float4(o0, o1, o2, o3);
        }

        zcur = znext;
    }
}

extern "C" void kernel_launch(void* const* d_in, const int* in_sizes, int n_in,
                              void* d_out, int out_size) {
    const float* x = (const float*)d_in[0];
    const float* m = (const float*)d_in[1];
    const float* n = (const float*)d_in[2];
    const float* I = (const float*)d_in[3];
    float* out = (float*)d_out;
    z_kernel<<<BATCH * TCH, NTHR>>>(x, I);
    xscan_kernel<<<BATCH, INPN>>>(x, out);
    rnn_kernel<<<BATCH, NTHR>>>(m, n, out);
}

// round 7
// speedup vs baseline: 1.0416x; 1.0416x over previous
#include <cuda_runtime.h>
#include <cstdint>

// MixtureLowRankRNN — GB300 sm_103a.
// Subspace identity: h_t ∈ colspan([m|I]) (h0=0) ⇒ outputs are basis coords:
//   y[:,t,0:4]  = a_s*S_{t+1},  S <- 0.9 S + u_t,  u_t = n^T tanh(h_t)
//   y[:,t,4:20] = 0.1*X_{t+1},  X <- 0.9 X + x_t
// Round 7: recurrence at 128 threads = 1 warp/SMSP (no arbiter dilation),
// 8 elements/thread. Z = 0.1*(x@I^T) precomputed (permuted layout, 2-step
// LDG prefetch). xscan chunk-parallel with 128-step decayed warmup.

#define RANKN 4
#define INPN  16
#define TLEN  1024
#define BATCH 32
#define TCH   32     // t-chunks per batch in z_kernel
#define XCH   8      // xscan chunks per batch (128 t each)

typedef unsigned long long u64;

// 128 MB scratch. Slot (b,t): 256 ulonglong2. rnn thread j reads
// [base+j]   = {pack2(Z_j,     Z_{j+128}), pack2(Z_{j+256}, Z_{j+384})}
// [base+128+j] = {pack2(Z_{j+512}, Z_{j+640}), pack2(Z_{j+768}, Z_{j+896})}
__device__ ulonglong2 g_z[BATCH * TLEN * 256];

__device__ __forceinline__ u64 pack2(float x, float y) {
    u64 r; asm("mov.b64 %0, {%1, %2};" : "=l"(r) : "f"(x), "f"(y)); return r;
}
__device__ __forceinline__ void unpack2(u64 v, float& x, float& y) {
    asm("mov.b64 {%0, %1}, %2;" : "=f"(x), "=f"(y) : "l"(v));
}
__device__ __forceinline__ u64 fma2(u64 a, u64 b, u64 c) {
    u64 d; asm("fma.rn.f32x2 %0, %1, %2, %3;" : "=l"(d) : "l"(a), "l"(b), "l"(c)); return d;
}
__device__ __forceinline__ u64 mul2(u64 a, u64 b) {
    u64 d; asm("mul.rn.f32x2 %0, %1, %2;" : "=l"(d) : "l"(a), "l"(b)); return d;
}
__device__ __forceinline__ u64 add2(u64 a, u64 b) {
    u64 d; asm("add.rn.f32x2 %0, %1, %2;" : "=l"(d) : "l"(a), "l"(b)); return d;
}
__device__ __forceinline__ float tanha(float x) {
    float r; asm("tanh.approx.f32 %0, %1;" : "=f"(r) : "f"(x)); return r;
}

// 6-shfl transposed warp reduce: returns warp-sum of p_{lane&3}.
__device__ __forceinline__ float warp_reduce4(float p0, float p1, float p2, float p3, int lane) {
    const bool b0 = lane & 1;
    const bool b1 = lane & 2;
    float sA = b0 ? p0 : p1;
    float rA = __shfl_xor_sync(0xffffffffu, sA, 1);
    float q0 = (b0 ? p1 : p0) + rA;
    float sB = b0 ? p2 : p3;
    float rB = __shfl_xor_sync(0xffffffffu, sB, 1);
    float q1 = (b0 ? p3 : p2) + rB;
    float sC = b1 ? q0 : q1;
    float rC = __shfl_xor_sync(0xffffffffu, sC, 2);
    float w  = (b1 ? q1 : q0) + rC;
    w += __shfl_xor_sync(0xffffffffu, w, 4);
    w += __shfl_xor_sync(0xffffffffu, w, 8);
    w += __shfl_xor_sync(0xffffffffu, w, 16);
    return w;
}

// ============ kernel 1: Z = 0.1 * x @ I^T, permuted layout ============
__global__ __launch_bounds__(256)
void z_kernel(const float* __restrict__ x, const float* __restrict__ I) {
    const int b   = blockIdx.x / TCH;
    const int tc  = blockIdx.x % TCH;
    const int tid = threadIdx.x;
    // element mapping matching rnn thread pair layout
    const int e0 = (tid < 128) ? tid : (tid + 384);
    const int e1 = e0 + 128, e2 = e0 + 256, e3 = e0 + 384;

    u64 Ia[INPN], Ib[INPN];
#pragma unroll
    for (int j = 0; j < INPN; j++) {
        Ia[j] = pack2(0.1f * I[e0 * INPN + j], 0.1f * I[e1 * INPN + j]);
        Ib[j] = pack2(0.1f * I[e2 * INPN + j], 0.1f * I[e3 * INPN + j]);
    }
    const float* xb = x + (size_t)b * TLEN * INPN;
    const int t0 = tc * (TLEN / TCH), t1 = t0 + (TLEN / TCH);

    for (int t = t0; t < t1; t++) {
        const float4* xr = (const float4*)(xb + (size_t)t * INPN);
        float4 f0 = xr[0], f1 = xr[1], f2 = xr[2], f3 = xr[3];
        u64 xd[INPN];
        xd[0]=pack2(f0.x,f0.x); xd[1]=pack2(f0.y,f0.y); xd[2]=pack2(f0.z,f0.z); xd[3]=pack2(f0.w,f0.w);
        xd[4]=pack2(f1.x,f1.x); xd[5]=pack2(f1.y,f1.y); xd[6]=pack2(f1.z,f1.z); xd[7]=pack2(f1.w,f1.w);
        xd[8]=pack2(f2.x,f2.x); xd[9]=pack2(f2.y,f2.y); xd[10]=pack2(f2.z,f2.z); xd[11]=pack2(f2.w,f2.w);
        xd[12]=pack2(f3.x,f3.x); xd[13]=pack2(f3.y,f3.y); xd[14]=pack2(f3.z,f3.z); xd[15]=pack2(f3.w,f3.w);

        u64 aA0 = fma2(Ia[4],  xd[4],  mul2(Ia[0], xd[0]));
        u64 aB0 = fma2(Ib[4],  xd[4],  mul2(Ib[0], xd[0]));
        u64 aA1 = fma2(Ia[5],  xd[5],  mul2(Ia[1], xd[1]));
        u64 aB1 = fma2(Ib[5],  xd[5],  mul2(Ib[1], xd[1]));
        u64 aA2 = fma2(Ia[6],  xd[6],  mul2(Ia[2], xd[2]));
        u64 aB2 = fma2(Ib[6],  xd[6],  mul2(Ib[2], xd[2]));
        u64 aA3 = fma2(Ia[7],  xd[7],  mul2(Ia[3], xd[3]));
        u64 aB3 = fma2(Ib[7],  xd[7],  mul2(Ib[3], xd[3]));
        aA0 = fma2(Ia[8],  xd[8],  aA0);  aB0 = fma2(Ib[8],  xd[8],  aB0);
        aA1 = fma2(Ia[9],  xd[9],  aA1);  aB1 = fma2(Ib[9],  xd[9],  aB1);
        aA2 = fma2(Ia[10], xd[10], aA2);  aB2 = fma2(Ib[10], xd[10], aB2);
        aA3 = fma2(Ia[11], xd[11], aA3);  aB3 = fma2(Ib[11], xd[11], aB3);
        aA0 = fma2(Ia[12], xd[12], aA0);  aB0 = fma2(Ib[12], xd[12], aB0);
        aA1 = fma2(Ia[13], xd[13], aA1);  aB1 = fma2(Ib[13], xd[13], aB1);
        aA2 = fma2(Ia[14], xd[14], aA2);  aB2 = fma2(Ib[14], xd[14], aB2);
        aA3 = fma2(Ia[15], xd[15], aA3);  aB3 = fma2(Ib[15], xd[15], aB3);
        u64 zA = add2(add2(aA0, aA1), add2(aA2, aA3));
        u64 zB = add2(add2(aB0, aB1), add2(aB2, aB3));

        ulonglong2 zo; zo.x = zA; zo.y = zB;
        g_z[((size_t)b * TLEN + t) * 256 + tid] = zo;
    }
}

// ====== kernel 2: y[:,:,4:20] = 0.1 * decayed x scan (chunked) ======
// 0.9^128 ~ 1.4e-6 so a 128-step warmup reproduces the scan to fp32 noise.
__global__ void xscan_kernel(const float* __restrict__ x, float* __restrict__ out) {
    const int b = blockIdx.x / XCH;
    const int c = blockIdx.x % XCH;
    const int j = threadIdx.x;       // 0..15
    const int tstart = c * (TLEN / XCH);
    const int w0 = (tstart >= 128) ? (tstart - 128) : 0;
    const float* xb = x   + (size_t)b * TLEN * INPN + j;
    float*       ob = out + (size_t)b * TLEN * 20 + 4 + j;
    float X = 0.f;
    for (int t = w0; t < tstart; t++)
        X = fmaf(0.9f, X, xb[(size_t)t * INPN]);
#pragma unroll 4
    for (int t = tstart; t < tstart + TLEN / XCH; t++) {
        X = fmaf(0.9f, X, xb[(size_t)t * INPN]);
        ob[(size_t)t * 20] = 0.1f * X;
    }
}

// ============ kernel 3: the serial recurrence (128 threads) ============
__global__ __launch_bounds__(128, 1)
void rnn_kernel(const float* __restrict__ m,
                const float* __restrict__ n,
                float* __restrict__ out)       // [B, T, 20]
{
    const int b    = blockIdx.x;
    const int j    = threadIdx.x;    // 0..127
    const int wid  = j >> 5;
    const int lane = j & 31;

    __shared__ float4 s_part[2][4];   // [buf][warp] partial {u0..u3}

    const float a_s = 0.1f * (500.0f / 1024.0f);

    // 4 pair-groups per thread: group g covers elements (j+256g, j+256g+128)
    u64 na[16], mc[16];   // [g*4 + r]
#pragma unroll
    for (int g = 0; g < 4; g++) {
        const int e0 = j + g * 256, e1 = e0 + 128;
#pragma unroll
        for (int r = 0; r < RANKN; r++) {
            na[g * 4 + r] = pack2(n[e0 * RANKN + r], n[e1 * RANKN + r]);
            mc[g * 4 + r] = pack2(a_s * m[e0 * RANKN + r], a_s * m[e1 * RANKN + r]);
        }
    }

    const u64 c9  = pack2(0.9f, 0.9f);
    const u64 asd = pack2(a_s, a_s);

    float* outb = out + (size_t)b * TLEN * 20;
    const ulonglong2* zp = g_z + (size_t)b * TLEN * 256 + j;

    u64 h[4]; h[0] = h[1] = h[2] = h[3] = 0ull;
    u64 S01 = 0ull, S23 = 0ull;      // warp0 lane0

    // 2-step Z prefetch pipeline (step < DRAM latency, so depth 2)
    ulonglong2 zc0 = zp[0],   zc1 = zp[128];
    ulonglong2 zn0 = zp[256], zn1 = zp[256 + 128];

    for (int t = 0; t < TLEN; t++) {
        // ---- issue Z_{t+2} loads (land 2 steps from now) ----
        const size_t tf = (t + 2 < TLEN) ? (size_t)(t + 2) : (size_t)(TLEN - 1);
        ulonglong2 zf0 = zp[tf * 256];
        ulonglong2 zf1 = zp[tf * 256 + 128];

        // ---- critical path: tanh(h), low-rank dot, warp reduce ----
        u64 th[4];
#pragma unroll
        for (int g = 0; g < 4; g++) {
            float a0, a1; unpack2(h[g], a0, a1);
            th[g] = pack2(tanha(a0), tanha(a1));
        }
        float p[4];
#pragma unroll
        for (int r = 0; r < RANKN; r++) {
            u64 t01 = fma2(na[4 + r],  th[1], mul2(na[r],      th[0]));
            u64 t23 = fma2(na[12 + r], th[3], mul2(na[8 + r],  th[2]));
            float lo, hi; unpack2(add2(t01, t23), lo, hi);
            p[r] = lo + hi;
        }
        float w = warp_reduce4(p[0], p[1], p[2], p[3], lane);
        if (lane < 4) ((float*)&s_part[t & 1][wid])[lane] = w;

        // ---- u-independent part: acc = 0.9 h + Z_t ----
        u64 acc0 = fma2(c9, h[0], zc0.x);
        u64 acc1 = fma2(c9, h[1], zc0.y);
        u64 acc2 = fma2(c9, h[2], zc1.x);
        u64 acc3 = fma2(c9, h[3], zc1.y);

        __syncthreads();   // the only barrier per step (4 warps)

        // ---- cross-warp combine: 4 LDS.128 + depth-2 tree ----
        const float4* sp = s_part[t & 1];
        ulonglong2 v0 = *(const ulonglong2*)&sp[0];
        ulonglong2 v1 = *(const ulonglong2*)&sp[1];
        ulonglong2 v2 = *(const ulonglong2*)&sp[2];
        ulonglong2 v3 = *(const ulonglong2*)&sp[3];
        u64 U01 = add2(add2(v0.x, v1.x), add2(v2.x, v3.x));
        u64 U23 = add2(add2(v0.y, v1.y), add2(v2.y, v3.y));

        float q0, q1, q2, q3;
        unpack2(U01, q0, q1); unpack2(U23, q2, q3);
        u64 U0d = pack2(q0, q0), U1d = pack2(q1, q1);
        u64 U2d = pack2(q2, q2), U3d = pack2(q3, q3);

        // h_{t+1} = acc + sum_r (a_s m_r) u_r
#pragma unroll
        for (int g = 0; g < 4; g++) {
            u64 cA = fma2(mc[g * 4 + 1], U1d, mul2(mc[g * 4],     U0d));
            u64 cB = fma2(mc[g * 4 + 3], U3d, mul2(mc[g * 4 + 2], U2d));
            u64 a  = (g == 0) ? acc0 : (g == 1) ? acc1 : (g == 2) ? acc2 : acc3;
            h[g] = add2(a, add2(cA, cB));
        }

        // ---- low-rank coordinate output (off critical path) ----
        if (wid == 0 && lane == 0) {
            S01 = fma2(c9, S01, U01);
            S23 = fma2(c9, S23, U23);
            float o0, o1, o2, o3;
            unpack2(mul2(asd, S01), o0, o1);
            unpack2(mul2(asd, S23), o2, o3);
            *(float4*)(outb + (size_t)t * 20) = make_float4(o0, o1, o2, o3);
        }

        // ---- rotate Z pipeline ----
        zc0 = zn0; zc1 = zn1;
        zn0 = zf0; zn1 = zf1;
    }
}

extern "C" void kernel_launch(void* const* d_in, const int* in_sizes, int n_in,
                              void* d_out, int out_size) {
    const float* x = (const float*)d_in[0];
    const float* m = (const float*)d_in[1];
    const float* n = (const float*)d_in[2];
    const float* I = (const float*)d_in[3];
    float* out = (float*)d_out;
    z_kernel<<<BATCH * TCH, 256>>>(x, I);
    xscan_kernel<<<BATCH * XCH, INPN>>>(x, out);
    rnn_kernel<<<BATCH, 128>>>(m, n, out);
}

// round 8
// speedup vs baseline: 1.0560x; 1.0139x over previous
#include <cuda_runtime.h>
#include <cstdint>

// MixtureLowRankRNN — GB300 sm_103a.
// Subspace identity: h_t ∈ colspan([m|I]) (h0=0) ⇒ outputs are basis coords:
//   y[:,t,0:4]  = a_s*S_{t+1},  S <- 0.9 S + u_t,  u_t = n^T tanh(h_t)
//   y[:,t,4:20] = 0.1*X_{t+1},  X <- 0.9 X + x_t
// Round 8: the block reduction is the whole step cost. Replace the 6-shfl
// float tree with ONE redux.sync.add.s32 per rank (fixed point, S=2^21 folded
// into the n weights; 1/S folded into m-side weights and output scale).
// Cross-warp combine = exact integer adds. Z = 0.1*(x@I^T) precomputed.

#define RANKN 4
#define INPN  16
#define TLEN  1024
#define BATCH 32
#define TCH   64     // t-chunks per batch in z_kernel (16 t each)
#define XCH   8      // xscan chunks per batch (128 t each)

#define S_Q   2097152.0f        // 2^21 fixed-point scale

typedef unsigned long long u64;

// 128 MB scratch. Slot (b,t) = 256 ulonglong2, thread-pair-permuted:
// slot[j]     = {pack2(Z_j,     Z_{j+128}), pack2(Z_{j+256}, Z_{j+384})}
// slot[j+128] = {pack2(Z_{j+512}, Z_{j+640}), pack2(Z_{j+768}, Z_{j+896})}
__device__ ulonglong2 g_z[BATCH * TLEN * 256];

__device__ __forceinline__ u64 pack2(float x, float y) {
    u64 r; asm("mov.b64 %0, {%1, %2};" : "=l"(r) : "f"(x), "f"(y)); return r;
}
__device__ __forceinline__ void unpack2(u64 v, float& x, float& y) {
    asm("mov.b64 {%0, %1}, %2;" : "=f"(x), "=f"(y) : "l"(v));
}
__device__ __forceinline__ u64 fma2(u64 a, u64 b, u64 c) {
    u64 d; asm("fma.rn.f32x2 %0, %1, %2, %3;" : "=l"(d) : "l"(a), "l"(b), "l"(c)); return d;
}
__device__ __forceinline__ u64 mul2(u64 a, u64 b) {
    u64 d; asm("mul.rn.f32x2 %0, %1, %2;" : "=l"(d) : "l"(a), "l"(b)); return d;
}
__device__ __forceinline__ u64 add2(u64 a, u64 b) {
    u64 d; asm("add.rn.f32x2 %0, %1, %2;" : "=l"(d) : "l"(a), "l"(b)); return d;
}
__device__ __forceinline__ float tanha(float x) {
    float r; asm("tanh.approx.f32 %0, %1;" : "=f"(r) : "f"(x)); return r;
}
__device__ __forceinline__ int redux_s32(int v) {
    int r; asm("redux.sync.add.s32 %0, %1, 0xffffffff;" : "=r"(r) : "r"(v)); return r;
}

// ============ kernel 1: Z = 0.1 * x @ I^T, permuted layout ============
__global__ __launch_bounds__(256)
void z_kernel(const float* __restrict__ x, const float* __restrict__ I) {
    const int b   = blockIdx.x / TCH;
    const int tc  = blockIdx.x % TCH;
    const int tid = threadIdx.x;
    const int e0 = (tid < 128) ? tid : (tid + 384);
    const int e1 = e0 + 128, e2 = e0 + 256, e3 = e0 + 384;

    u64 Ia[INPN], Ib[INPN];
#pragma unroll
    for (int j = 0; j < INPN; j++) {
        Ia[j] = pack2(0.1f * I[e0 * INPN + j], 0.1f * I[e1 * INPN + j]);
        Ib[j] = pack2(0.1f * I[e2 * INPN + j], 0.1f * I[e3 * INPN + j]);
    }
    const float* xb = x + (size_t)b * TLEN * INPN;
    const int t0 = tc * (TLEN / TCH), t1 = t0 + (TLEN / TCH);

    // software pipeline: x for t loaded one iteration ahead
    const float4* xr = (const float4*)(xb + (size_t)t0 * INPN);
    float4 f0 = xr[0], f1 = xr[1], f2 = xr[2], f3 = xr[3];

    for (int t = t0; t < t1; t++) {
        const int tn = (t + 1 < t1) ? (t + 1) : t;
        const float4* xrn = (const float4*)(xb + (size_t)tn * INPN);
        float4 g0 = xrn[0], g1 = xrn[1], g2 = xrn[2], g3 = xrn[3];

        u64 xd[INPN];
        xd[0]=pack2(f0.x,f0.x); xd[1]=pack2(f0.y,f0.y); xd[2]=pack2(f0.z,f0.z); xd[3]=pack2(f0.w,f0.w);
        xd[4]=pack2(f1.x,f1.x); xd[5]=pack2(f1.y,f1.y); xd[6]=pack2(f1.z,f1.z); xd[7]=pack2(f1.w,f1.w);
        xd[8]=pack2(f2.x,f2.x); xd[9]=pack2(f2.y,f2.y); xd[10]=pack2(f2.z,f2.z); xd[11]=pack2(f2.w,f2.w);
        xd[12]=pack2(f3.x,f3.x); xd[13]=pack2(f3.y,f3.y); xd[14]=pack2(f3.z,f3.z); xd[15]=pack2(f3.w,f3.w);

        u64 aA0 = fma2(Ia[4],  xd[4],  mul2(Ia[0], xd[0]));
        u64 aB0 = fma2(Ib[4],  xd[4],  mul2(Ib[0], xd[0]));
        u64 aA1 = fma2(Ia[5],  xd[5],  mul2(Ia[1], xd[1]));
        u64 aB1 = fma2(Ib[5],  xd[5],  mul2(Ib[1], xd[1]));
        u64 aA2 = fma2(Ia[6],  xd[6],  mul2(Ia[2], xd[2]));
        u64 aB2 = fma2(Ib[6],  xd[6],  mul2(Ib[2], xd[2]));
        u64 aA3 = fma2(Ia[7],  xd[7],  mul2(Ia[3], xd[3]));
        u64 aB3 = fma2(Ib[7],  xd[7],  mul2(Ib[3], xd[3]));
        aA0 = fma2(Ia[8],  xd[8],  aA0);  aB0 = fma2(Ib[8],  xd[8],  aB0);
        aA1 = fma2(Ia[9],  xd[9],  aA1);  aB1 = fma2(Ib[9],  xd[9],  aB1);
        aA2 = fma2(Ia[10], xd[10], aA2);  aB2 = fma2(Ib[10], xd[10], aB2);
        aA3 = fma2(Ia[11], xd[11], aA3);  aB3 = fma2(Ib[11], xd[11], aB3);
        aA0 = fma2(Ia[12], xd[12], aA0);  aB0 = fma2(Ib[12], xd[12], aB0);
        aA1 = fma2(Ia[13], xd[13], aA1);  aB1 = fma2(Ib[13], xd[13], aB1);
        aA2 = fma2(Ia[14], xd[14], aA2);  aB2 = fma2(Ib[14], xd[14], aB2);
        aA3 = fma2(Ia[15], xd[15], aA3);  aB3 = fma2(Ib[15], xd[15], aB3);
        ulonglong2 zo;
        zo.x = add2(add2(aA0, aA1), add2(aA2, aA3));
        zo.y = add2(add2(aB0, aB1), add2(aB2, aB3));
        g_z[((size_t)b * TLEN + t) * 256 + tid] = zo;

        f0 = g0; f1 = g1; f2 = g2; f3 = g3;
    }
}

// ====== kernel 2: y[:,:,4:20] = 0.1 * decayed x scan (chunked) ======
// 0.9^128 ~ 1.4e-6 so a 128-step warmup reproduces the scan to fp32 noise.
__global__ void xscan_kernel(const float* __restrict__ x, float* __restrict__ out) {
    const int b = blockIdx.x / XCH;
    const int c = blockIdx.x % XCH;
    const int j = threadIdx.x;       // 0..15
    const int tstart = c * (TLEN / XCH);
    const int w0 = (tstart >= 128) ? (tstart - 128) : 0;
    const float* xb = x   + (size_t)b * TLEN * INPN + j;
    float*       ob = out + (size_t)b * TLEN * 20 + 4 + j;
    float X = 0.f;
    for (int t = w0; t < tstart; t++)
        X = fmaf(0.9f, X, xb[(size_t)t * INPN]);
#pragma unroll 4
    for (int t = tstart; t < tstart + TLEN / XCH; t++) {
        X = fmaf(0.9f, X, xb[(size_t)t * INPN]);
        ob[(size_t)t * 20] = 0.1f * X;
    }
}

// ============ kernel 3: the serial recurrence (128 threads) ============
__global__ __launch_bounds__(128, 1)
void rnn_kernel(const float* __restrict__ m,
                const float* __restrict__ n,
                float* __restrict__ out)       // [B, T, 20]
{
    const int b    = blockIdx.x;
    const int j    = threadIdx.x;    // 0..127
    const int wid  = j >> 5;
    const int lane = j & 31;

    __shared__ int4 s_ipart[2][4];   // [buf][warp] integer partial {u0..u3}

    const float a_s  = 0.1f * (500.0f / 1024.0f);
    const float invS = 1.0f / S_Q;

    // 4 pair-groups per thread: group g covers elements (j+256g, j+256g+128)
    // n pre-scaled by S_Q (fixed-point domain); m carries a_s/S_Q.
    u64 na[16], mc[16];   // [g*4 + r]
#pragma unroll
    for (int g = 0; g < 4; g++) {
        const int e0 = j + g * 256, e1 = e0 + 128;
#pragma unroll
        for (int r = 0; r < RANKN; r++) {
            na[g * 4 + r] = pack2(S_Q * n[e0 * RANKN + r], S_Q * n[e1 * RANKN + r]);
            mc[g * 4 + r] = pack2(a_s * invS * m[e0 * RANKN + r],
                                  a_s * invS * m[e1 * RANKN + r]);
        }
    }

    const u64 c9   = pack2(0.9f, 0.9f);
    const u64 asq  = pack2(a_s * invS, a_s * invS);   // output scale

    float* outb = out + (size_t)b * TLEN * 20;
    const ulonglong2* zp = g_z + (size_t)b * TLEN * 256 + j;

    u64 h[4]; h[0] = h[1] = h[2] = h[3] = 0ull;
    u64 S01 = 0ull, S23 = 0ull;      // warp0 lane0, scaled domain (S_Q x u)

    // 2-step Z prefetch pipeline
    ulonglong2 zc0 = zp[0],   zc1 = zp[128];
    ulonglong2 zn0 = zp[256], zn1 = zp[256 + 128];

    for (int t = 0; t < TLEN; t++) {
        // ---- issue Z_{t+2} loads (land 2 steps from now) ----
        const size_t tf = (t + 2 < TLEN) ? (size_t)(t + 2) : (size_t)(TLEN - 1);
        ulonglong2 zf0 = zp[tf * 256];
        ulonglong2 zf1 = zp[tf * 256 + 128];

        // ---- critical path: tanh(h), scaled low-rank dot, int redux ----
        u64 th[4];
#pragma unroll
        for (int g = 0; g < 4; g++) {
            float a0, a1; unpack2(h[g], a0, a1);
            th[g] = pack2(tanha(a0), tanha(a1));
        }
        int pi[4];
#pragma unroll
        for (int r = 0; r < RANKN; r++) {
            u64 t01 = fma2(na[4 + r],  th[1], mul2(na[r],     th[0]));
            u64 t23 = fma2(na[12 + r], th[3], mul2(na[8 + r], th[2]));
            float lo, hi; unpack2(add2(t01, t23), lo, hi);
            pi[r] = __float2int_rn(lo + hi);          // fixed point
            pi[r] = redux_s32(pi[r]);                 // 1-instr warp sum
        }
        if (lane == 0) s_ipart[t & 1][wid] = make_int4(pi[0], pi[1], pi[2], pi[3]);

        // ---- u-independent part: acc = 0.9 h + Z_t ----
        u64 acc0 = fma2(c9, h[0], zc0.x);
        u64 acc1 = fma2(c9, h[1], zc0.y);
        u64 acc2 = fma2(c9, h[2], zc1.x);
        u64 acc3 = fma2(c9, h[3], zc1.y);

        __syncthreads();   // the only barrier per step (4 warps)

        // ---- cross-warp combine: 4 LDS.128 + exact integer adds ----
        const int4* sp = s_ipart[t & 1];
        int4 v0 = sp[0], v1 = sp[1], v2 = sp[2], v3 = sp[3];
        int U0 = (v0.x + v1.x) + (v2.x + v3.x);
        int U1 = (v0.y + v1.y) + (v2.y + v3.y);
        int U2 = (v0.z + v1.z) + (v2.z + v3.z);
        int U3 = (v0.w + v1.w) + (v2.w + v3.w);

        float uf0 = (float)U0, uf1 = (float)U1;   // S_Q x u_r
        float uf2 = (float)U2, uf3 = (float)U3;
        u64 U0d = pack2(uf0, uf0), U1d = pack2(uf1, uf1);
        u64 U2d = pack2(uf2, uf2), U3d = pack2(uf3, uf3);

        // h_{t+1} = acc + sum_r (a_s m_r / S_Q) * (S_Q u_r)
#pragma unroll
        for (int g = 0; g < 4; g++) {
            u64 cA = fma2(mc[g * 4 + 1], U1d, mul2(mc[g * 4],     U0d));
            u64 cB = fma2(mc[g * 4 + 3], U3d, mul2(mc[g * 4 + 2], U2d));
            u64 a  = (g == 0) ? acc0 : (g == 1) ? acc1 : (g == 2) ? acc2 : acc3;
            h[g] = add2(a, add2(cA, cB));
        }

        // ---- low-rank coordinate output (off critical path) ----
        if (wid == 0 && lane == 0) {
            S01 = fma2(c9, S01, pack2(uf0, uf1));
            S23 = fma2(c9, S23, pack2(uf2, uf3));
            float o0, o1, o2, o3;
            unpack2(mul2(asq, S01), o0, o1);
            unpack2(mul2(asq, S23), o2, o3);
            *(float4*)(outb + (size_t)t * 20) = make_float4(o0, o1, o2, o3);
        }

        // ---- rotate Z pipeline ----
        zc0 = zn0; zc1 = zn1;
        zn0 = zf0; zn1 = zf1;
    }
}

extern "C" void kernel_launch(void* const* d_in, const int* in_sizes, int n_in,
                              void* d_out, int out_size) {
    const float* x = (const float*)d_in[0];
    const float* m = (const float*)d_in[1];
    const float* n = (const float*)d_in[2];
    const float* I = (const float*)d_in[3];
    float* out = (float*)d_out;
    z_kernel<<<BATCH * TCH, 256>>>(x, I);
    xscan_kernel<<<BATCH * XCH, INPN>>>(x, out);
    rnn_kernel<<<BATCH, 128>>>(m, n, out);
}

// round 9
// speedup vs baseline: 1.6208x; 1.5348x over previous
#include <cuda_runtime.h>
#include <cstdint>

// MixtureLowRankRNN — GB300 sm_103a.
// Subspace identity: h_t ∈ colspan([m|I]) (h0=0) ⇒ outputs are basis coords:
//   y[:,t,0:4]  = a_s*S_{t+1},  S <- 0.9 S + u_t,  u_t = n^T tanh(h_t)
//   y[:,t,4:20] = 0.1*X_{t+1},  X <- 0.9 X + x_t
// Round 9 key fix: the Z prefetch previously had only 1 step of real slack
// (register rotation consumed the just-issued LDG), making every step pay a
// DRAM round trip (~800 cyc — the observed invariant). Now an 8-slot register
// ring + x8 unroll gives each load 8 steps (~2400 cyc) before its consumer.

#define RANKN 4
#define INPN  16
#define TLEN  1024
#define BATCH 32
#define ZT    16     // timesteps per z_kernel CTA
#define XCH   8      // xscan chunks per batch (128 t each)

#define S_Q   2097152.0f        // 2^21 fixed-point scale

typedef unsigned long long u64;

// 128 MB scratch. Slot (b,t) = 256 ulonglong2, thread-pair-permuted:
// slot[j]     = {pack2(Z_j,     Z_{j+128}), pack2(Z_{j+256}, Z_{j+384})}
// slot[j+128] = {pack2(Z_{j+512}, Z_{j+640}), pack2(Z_{j+768}, Z_{j+896})}
__device__ ulonglong2 g_z[BATCH * TLEN * 256];

__device__ __forceinline__ u64 pack2(float x, float y) {
    u64 r; asm("mov.b64 %0, {%1, %2};" : "=l"(r) : "f"(x), "f"(y)); return r;
}
__device__ __forceinline__ void unpack2(u64 v, float& x, float& y) {
    asm("mov.b64 {%0, %1}, %2;" : "=f"(x), "=f"(y) : "l"(v));
}
__device__ __forceinline__ u64 fma2(u64 a, u64 b, u64 c) {
    u64 d; asm("fma.rn.f32x2 %0, %1, %2, %3;" : "=l"(d) : "l"(a), "l"(b), "l"(c)); return d;
}
__device__ __forceinline__ u64 mul2(u64 a, u64 b) {
    u64 d; asm("mul.rn.f32x2 %0, %1, %2;" : "=l"(d) : "l"(a), "l"(b)); return d;
}
__device__ __forceinline__ u64 add2(u64 a, u64 b) {
    u64 d; asm("add.rn.f32x2 %0, %1, %2;" : "=l"(d) : "l"(a), "l"(b)); return d;
}
__device__ __forceinline__ float tanha(float x) {
    float r; asm("tanh.approx.f32 %0, %1;" : "=f"(r) : "f"(x)); return r;
}
__device__ __forceinline__ int redux_s32(int v) {
    int r; asm("redux.sync.add.s32 %0, %1, 0xffffffff;" : "=r"(r) : "r"(v)); return r;
}

// ============ kernel 1: Z = 0.1 * x @ I^T, permuted layout ============
// Whole 16-step x chunk staged in smem once (one DRAM trip per CTA), then
// the 16 step computations run from LDS broadcasts with no memory stalls.
__global__ __launch_bounds__(256)
void z_kernel(const float* __restrict__ x, const float* __restrict__ I) {
    const int b   = blockIdx.x / (TLEN / ZT);
    const int tc  = blockIdx.x % (TLEN / ZT);
    const int tid = threadIdx.x;
    const int e0 = (tid < 128) ? tid : (tid + 384);
    const int e1 = e0 + 128, e2 = e0 + 256, e3 = e0 + 384;

    __shared__ float4 sx[ZT * INPN / 4];   // 1 KB: x[t0..t0+15][0..15]

    const int t0 = tc * ZT;
    if (tid < ZT * INPN / 4)
        sx[tid] = ((const float4*)(x + ((size_t)b * TLEN + t0) * INPN))[tid];

    u64 Ia[INPN], Ib[INPN];
#pragma unroll
    for (int j = 0; j < INPN; j++) {
        Ia[j] = pack2(0.1f * I[e0 * INPN + j], 0.1f * I[e1 * INPN + j]);
        Ib[j] = pack2(0.1f * I[e2 * INPN + j], 0.1f * I[e3 * INPN + j]);
    }
    __syncthreads();

    ulonglong2* zout = &g_z[((size_t)b * TLEN + t0) * 256 + tid];

#pragma unroll 2
    for (int u = 0; u < ZT; u++) {
        float4 f0 = sx[u * 4 + 0], f1 = sx[u * 4 + 1];
        float4 f2 = sx[u * 4 + 2], f3 = sx[u * 4 + 3];
        u64 xd[INPN];
        xd[0]=pack2(f0.x,f0.x); xd[1]=pack2(f0.y,f0.y); xd[2]=pack2(f0.z,f0.z); xd[3]=pack2(f0.w,f0.w);
        xd[4]=pack2(f1.x,f1.x); xd[5]=pack2(f1.y,f1.y); xd[6]=pack2(f1.z,f1.z); xd[7]=pack2(f1.w,f1.w);
        xd[8]=pack2(f2.x,f2.x); xd[9]=pack2(f2.y,f2.y); xd[10]=pack2(f2.z,f2.z); xd[11]=pack2(f2.w,f2.w);
        xd[12]=pack2(f3.x,f3.x); xd[13]=pack2(f3.y,f3.y); xd[14]=pack2(f3.z,f3.z); xd[15]=pack2(f3.w,f3.w);

        u64 aA0 = fma2(Ia[4],  xd[4],  mul2(Ia[0], xd[0]));
        u64 aB0 = fma2(Ib[4],  xd[4],  mul2(Ib[0], xd[0]));
        u64 aA1 = fma2(Ia[5],  xd[5],  mul2(Ia[1], xd[1]));
        u64 aB1 = fma2(Ib[5],  xd[5],  mul2(Ib[1], xd[1]));
        u64 aA2 = fma2(Ia[6],  xd[6],  mul2(Ia[2], xd[2]));
        u64 aB2 = fma2(Ib[6],  xd[6],  mul2(Ib[2], xd[2]));
        u64 aA3 = fma2(Ia[7],  xd[7],  mul2(Ia[3], xd[3]));
        u64 aB3 = fma2(Ib[7],  xd[7],  mul2(Ib[3], xd[3]));
        aA0 = fma2(Ia[8],  xd[8],  aA0);  aB0 = fma2(Ib[8],  xd[8],  aB0);
        aA1 = fma2(Ia[9],  xd[9],  aA1);  aB1 = fma2(Ib[9],  xd[9],  aB1);
        aA2 = fma2(Ia[10], xd[10], aA2);  aB2 = fma2(Ib[10], xd[10], aB2);
        aA3 = fma2(Ia[11], xd[11], aA3);  aB3 = fma2(Ib[11], xd[11], aB3);
        aA0 = fma2(Ia[12], xd[12], aA0);  aB0 = fma2(Ib[12], xd[12], aB0);
        aA1 = fma2(Ia[13], xd[13], aA1);  aB1 = fma2(Ib[13], xd[13], aB1);
        aA2 = fma2(Ia[14], xd[14], aA2);  aB2 = fma2(Ib[14], xd[14], aB2);
        aA3 = fma2(Ia[15], xd[15], aA3);  aB3 = fma2(Ib[15], xd[15], aB3);
        ulonglong2 zo;
        zo.x = add2(add2(aA0, aA1), add2(aA2, aA3));
        zo.y = add2(add2(aB0, aB1), add2(aB2, aB3));
        zout[(size_t)u * 256] = zo;
    }
}

// ====== kernel 2: y[:,:,4:20] = 0.1 * decayed x scan (chunked) ======
// 0.9^128 ~ 1.4e-6 so a 128-step warmup reproduces the scan to fp32 noise.
__global__ void xscan_kernel(const float* __restrict__ x, float* __restrict__ out) {
    const int b = blockIdx.x / XCH;
    const int c = blockIdx.x % XCH;
    const int j = threadIdx.x;       // 0..15
    const int tstart = c * (TLEN / XCH);
    const int w0 = (tstart >= 128) ? (tstart - 128) : 0;
    const float* xb = x   + (size_t)b * TLEN * INPN + j;
    float*       ob = out + (size_t)b * TLEN * 20 + 4 + j;
    float X = 0.f;
    for (int t = w0; t < tstart; t++)
        X = fmaf(0.9f, X, xb[(size_t)t * INPN]);
#pragma unroll 4
    for (int t = tstart; t < tstart + TLEN / XCH; t++) {
        X = fmaf(0.9f, X, xb[(size_t)t * INPN]);
        ob[(size_t)t * 20] = 0.1f * X;
    }
}

// ============ kernel 3: the serial recurrence (128 threads) ============
__global__ __launch_bounds__(128, 1)
void rnn_kernel(const float* __restrict__ m,
                const float* __restrict__ n,
                float* __restrict__ out)       // [B, T, 20]
{
    const int b    = blockIdx.x;
    const int j    = threadIdx.x;    // 0..127
    const int wid  = j >> 5;
    const int lane = j & 31;

    __shared__ int4 s_ipart[2][4];   // [buf][warp] integer partial {u0..u3}

    const float a_s  = 0.1f * (500.0f / 1024.0f);
    const float invS = 1.0f / S_Q;

    // 4 pair-groups per thread: group g covers elements (j+256g, j+256g+128)
    u64 na[16], mc[16];   // [g*4 + r]
#pragma unroll
    for (int g = 0; g < 4; g++) {
        const int e0 = j + g * 256, e1 = e0 + 128;
#pragma unroll
        for (int r = 0; r < RANKN; r++) {
            na[g * 4 + r] = pack2(S_Q * n[e0 * RANKN + r], S_Q * n[e1 * RANKN + r]);
            mc[g * 4 + r] = pack2(a_s * invS * m[e0 * RANKN + r],
                                  a_s * invS * m[e1 * RANKN + r]);
        }
    }

    const u64 c9  = pack2(0.9f, 0.9f);
    const u64 asq = pack2(a_s * invS, a_s * invS);

    float* outb = out + (size_t)b * TLEN * 20;
    const ulonglong2* zp = g_z + (size_t)b * TLEN * 256 + j;

    u64 h[4]; h[0] = h[1] = h[2] = h[3] = 0ull;
    u64 S01 = 0ull, S23 = 0ull;      // warp0 lane0, scaled domain

    // 8-slot Z register ring: slot u holds Z for the next step with t%8==u.
    ulonglong2 zb0[8], zb1[8];
#pragma unroll
    for (int u = 0; u < 8; u++) {
        zb0[u] = zp[(size_t)u * 256];
        zb1[u] = zp[(size_t)u * 256 + 128];
    }

    for (int tb = 0; tb < TLEN; tb += 8) {
#pragma unroll
        for (int u = 0; u < 8; u++) {
            const int t = tb + u;

            // ---- critical path: tanh(h), scaled low-rank dot, int redux ----
            u64 th[4];
#pragma unroll
            for (int g = 0; g < 4; g++) {
                float a0, a1; unpack2(h[g], a0, a1);
                th[g] = pack2(tanha(a0), tanha(a1));
            }
            int pi[4];
#pragma unroll
            for (int r = 0; r < RANKN; r++) {
                u64 t01 = fma2(na[4 + r],  th[1], mul2(na[r],     th[0]));
                u64 t23 = fma2(na[12 + r], th[3], mul2(na[8 + r], th[2]));
                float lo, hi; unpack2(add2(t01, t23), lo, hi);
                pi[r] = __float2int_rn(lo + hi);
                pi[r] = redux_s32(pi[r]);
            }
            if (lane == 0) s_ipart[t & 1][wid] = make_int4(pi[0], pi[1], pi[2], pi[3]);

            // ---- u-independent part: acc = 0.9 h + Z_t ----
            u64 acc0 = fma2(c9, h[0], zb0[u].x);
            u64 acc1 = fma2(c9, h[1], zb0[u].y);
            u64 acc2 = fma2(c9, h[2], zb1[u].x);
            u64 acc3 = fma2(c9, h[3], zb1[u].y);

            // ---- reload this ring slot for t+8 (consumer 8 steps away) ----
            {
                int tf = t + 8; if (tf >= TLEN) tf = TLEN - 1;
                zb0[u] = zp[(size_t)tf * 256];
                zb1[u] = zp[(size_t)tf * 256 + 128];
            }

            __syncthreads();   // the only barrier per step (4 warps)

            // ---- cross-warp combine: 4 LDS.128 + exact integer adds ----
            const int4* sp = s_ipart[t & 1];
            int4 v0 = sp[0], v1 = sp[1], v2 = sp[2], v3 = sp[3];
            int U0 = (v0.x + v1.x) + (v2.x + v3.x);
            int U1 = (v0.y + v1.y) + (v2.y + v3.y);
            int U2 = (v0.z + v1.z) + (v2.z + v3.z);
            int U3 = (v0.w + v1.w) + (v2.w + v3.w);

            float uf0 = (float)U0, uf1 = (float)U1;
            float uf2 = (float)U2, uf3 = (float)U3;
            u64 U0d = pack2(uf0, uf0), U1d = pack2(uf1, uf1);
            u64 U2d = pack2(uf2, uf2), U3d = pack2(uf3, uf3);

            // h_{t+1} = acc + sum_r (a_s m_r / S_Q) * (S_Q u_r)
#pragma unroll
            for (int g = 0; g < 4; g++) {
                u64 cA = fma2(mc[g * 4 + 1], U1d, mul2(mc[g * 4],     U0d));
                u64 cB = fma2(mc[g * 4 + 3], U3d, mul2(mc[g * 4 + 2], U2d));
                u64 a  = (g == 0) ? acc0 : (g == 1) ? acc1 : (g == 2) ? acc2 : acc3;
                h[g] = add2(a, add2(cA, cB));
            }

            // ---- low-rank coordinate output (off critical path) ----
            if (wid == 0 && lane == 0) {
                S01 = fma2(c9, S01, pack2(uf0, uf1));
                S23 = fma2(c9, S23, pack2(uf2, uf3));
                float o0, o1, o2, o3;
                unpack2(mul2(asq, S01), o0, o1);
                unpack2(mul2(asq, S23), o2, o3);
                *(float4*)(outb + (size_t)t * 20) = make_float4(o0, o1, o2, o3);
            }
        }
    }
}

extern "C" void kernel_launch(void* const* d_in, const int* in_sizes, int n_in,
                              void* d_out, int out_size) {
    const float* x = (const float*)d_in[0];
    const float* m = (const float*)d_in[1];
    const float* n = (const float*)d_in[2];
    const float* I = (const float*)d_in[3];
    float* out = (float*)d_out;
    z_kernel<<<BATCH * (TLEN / ZT), 256>>>(x, I);
    xscan_kernel<<<BATCH * XCH, INPN>>>(x, out);
    rnn_kernel<<<BATCH, 128>>>(m, n, out);
}

// round 10
// speedup vs baseline: 1.6994x; 1.0485x over previous
#include <cuda_runtime.h>
#include <cstdint>

// MixtureLowRankRNN — GB300 sm_103a. Single fused kernel.
// Subspace identity: h_t ∈ colspan([m|I]) (h0=0) ⇒ outputs are basis coords:
//   y[:,t,0:4]  = a_s*S_{t+1},  S <- 0.9 S + u_t,  u_t = n^T tanh(h_t)
//   y[:,t,4:20] = 0.1*X_{t+1},  X <- 0.9 X + x_t
// Round 10: whole batch's x (64KB) staged pre-duplicated in 128KB dynamic
// smem at kernel start -> the 1024-step loop touches DRAM only for outputs.
// No Z scratch, no separate kernels. Int fixed-point redux reduction (S=2^21).

#define RANKN 4
#define INPN  16
#define TLEN  1024
#define BATCH 32
#define NTHR  256

#define S_Q   2097152.0f     // 2^21 fixed-point scale

typedef unsigned long long u64;

#define SMEM_X_BYTES  (TLEN * INPN * 8)          // duplicated pairs: 128 KB
#define SMEM_TOTAL    (SMEM_X_BYTES + 2 * 8 * 16)

__device__ __forceinline__ u64 pack2(float x, float y) {
    u64 r; asm("mov.b64 %0, {%1, %2};" : "=l"(r) : "f"(x), "f"(y)); return r;
}
__device__ __forceinline__ void unpack2(u64 v, float& x, float& y) {
    asm("mov.b64 {%0, %1}, %2;" : "=f"(x), "=f"(y) : "l"(v));
}
__device__ __forceinline__ u64 fma2(u64 a, u64 b, u64 c) {
    u64 d; asm("fma.rn.f32x2 %0, %1, %2, %3;" : "=l"(d) : "l"(a), "l"(b), "l"(c)); return d;
}
__device__ __forceinline__ u64 mul2(u64 a, u64 b) {
    u64 d; asm("mul.rn.f32x2 %0, %1, %2;" : "=l"(d) : "l"(a), "l"(b)); return d;
}
__device__ __forceinline__ u64 add2(u64 a, u64 b) {
    u64 d; asm("add.rn.f32x2 %0, %1, %2;" : "=l"(d) : "l"(a), "l"(b)); return d;
}
__device__ __forceinline__ float tanha(float x) {
    float r; asm("tanh.approx.f32 %0, %1;" : "=f"(r) : "f"(x)); return r;
}
__device__ __forceinline__ int redux_s32(int v) {
    int r; asm("redux.sync.add.s32 %0, %1, 0xffffffff;" : "=r"(r) : "r"(v)); return r;
}

__global__ __launch_bounds__(NTHR, 1)
void rnn_fused(const float* __restrict__ x,   // [B, T, 16]
               const float* __restrict__ m,   // [H, 4]
               const float* __restrict__ n,   // [H, 4]
               const float* __restrict__ I,   // [H, 16]
               float* __restrict__ out)       // [B, T, 20]
{
    extern __shared__ char smem[];
    u64*  s_xd    = (u64*)smem;                        // [TLEN*16] duplicated x
    int4* s_ipart = (int4*)(smem + SMEM_X_BYTES);      // [2][8]

    const int b    = blockIdx.x;
    const int tid  = threadIdx.x;
    const int wid  = tid >> 5;
    const int lane = tid & 31;

    const float a_s  = 0.1f * (500.0f / 1024.0f);
    const float invS = 1.0f / S_Q;

    // ---- stage the whole batch's x into smem, duplicated as f32x2 pairs ----
    const float* xb = x + (size_t)b * TLEN * INPN;
    {
        const float4* xr4 = (const float4*)xb;
        for (int idx = tid; idx < TLEN * INPN / 4; idx += NTHR) {
            float4 f = xr4[idx];
            s_xd[idx * 4 + 0] = pack2(f.x, f.x);
            s_xd[idx * 4 + 1] = pack2(f.y, f.y);
            s_xd[idx * 4 + 2] = pack2(f.z, f.z);
            s_xd[idx * 4 + 3] = pack2(f.w, f.w);
        }
    }

    // ---- weights in registers (pairs: A=(tid,tid+256), B=(tid+512,tid+768)) ----
    const int eA0 = tid,       eA1 = tid + 256;
    const int eB0 = tid + 512, eB1 = tid + 768;

    u64 naA[RANKN], naB[RANKN], mcA[RANKN], mcB[RANKN], Ia[INPN], Ib[INPN];
#pragma unroll
    for (int r = 0; r < RANKN; r++) {
        naA[r] = pack2(S_Q * n[eA0 * RANKN + r], S_Q * n[eA1 * RANKN + r]);
        naB[r] = pack2(S_Q * n[eB0 * RANKN + r], S_Q * n[eB1 * RANKN + r]);
        mcA[r] = pack2(a_s * invS * m[eA0 * RANKN + r], a_s * invS * m[eA1 * RANKN + r]);
        mcB[r] = pack2(a_s * invS * m[eB0 * RANKN + r], a_s * invS * m[eB1 * RANKN + r]);
    }
#pragma unroll
    for (int j = 0; j < INPN; j++) {
        Ia[j] = pack2(0.1f * I[eA0 * INPN + j], 0.1f * I[eA1 * INPN + j]);
        Ib[j] = pack2(0.1f * I[eB0 * INPN + j], 0.1f * I[eB1 * INPN + j]);
    }

    const u64 c9  = pack2(0.9f, 0.9f);
    const u64 asq = pack2(a_s * invS, a_s * invS);

    float* outb = out + (size_t)b * TLEN * 20;

    u64 hA = 0ull, hB = 0ull;
    u64 S01 = 0ull, S23 = 0ull;      // warp0 lane0, scaled domain
    float X = 0.f;                   // warp1 lanes 0..15

    __syncthreads();   // x staging complete

    for (int t = 0; t < TLEN; t++) {
        // ---- critical path: tanh(h), scaled low-rank dot, int redux ----
        float a0, a1, b0v, b1v;
        unpack2(hA, a0, a1); unpack2(hB, b0v, b1v);
        u64 thA = pack2(tanha(a0), tanha(a1));
        u64 thB = pack2(tanha(b0v), tanha(b1v));

        int pi[4];
#pragma unroll
        for (int r = 0; r < RANKN; r++) {
            float lo, hi; unpack2(fma2(naB[r], thB, mul2(naA[r], thA)), lo, hi);
            pi[r] = redux_s32(__float2int_rn(lo + hi));
        }
        if (lane == 0) s_ipart[(t & 1) * 8 + wid] = make_int4(pi[0], pi[1], pi[2], pi[3]);

        // ---- u-independent update from smem x: 8 LDS.128 + 4 parallel chains ----
        const ulonglong2* xp = (const ulonglong2*)(s_xd + (size_t)t * INPN);
        ulonglong2 xq0 = xp[0], xq1 = xp[1], xq2 = xp[2], xq3 = xp[3];
        u64 aA0 = fma2(c9, hA, mul2(Ia[0], xq0.x));
        u64 aB0 = fma2(c9, hB, mul2(Ib[0], xq0.x));
        u64 aA1 = fma2(Ia[2], xq1.x, mul2(Ia[1], xq0.y));
        u64 aB1 = fma2(Ib[2], xq1.x, mul2(Ib[1], xq0.y));
        u64 aA2 = fma2(Ia[4], xq2.x, mul2(Ia[3], xq1.y));
        u64 aB2 = fma2(Ib[4], xq2.x, mul2(Ib[3], xq1.y));
        u64 aA3 = fma2(Ia[6], xq3.x, mul2(Ia[5], xq2.y));
        u64 aB3 = fma2(Ib[6], xq3.x, mul2(Ib[5], xq2.y));
        ulonglong2 xq4 = xp[4], xq5 = xp[5], xq6 = xp[6], xq7 = xp[7];
        aA0 = fma2(Ia[7],  xq3.y, aA0);  aB0 = fma2(Ib[7],  xq3.y, aB0);
        aA1 = fma2(Ia[8],  xq4.x, aA1);  aB1 = fma2(Ib[8],  xq4.x, aB1);
        aA2 = fma2(Ia[9],  xq4.y, aA2);  aB2 = fma2(Ib[9],  xq4.y, aB2);
        aA3 = fma2(Ia[10], xq5.x, aA3);  aB3 = fma2(Ib[10], xq5.x, aB3);
        aA0 = fma2(Ia[11], xq5.y, aA0);  aB0 = fma2(Ib[11], xq5.y, aB0);
        aA1 = fma2(Ia[12], xq6.x, aA1);  aB1 = fma2(Ib[12], xq6.x, aB1);
        aA2 = fma2(Ia[13], xq6.y, aA2);  aB2 = fma2(Ib[13], xq6.y, aB2);
        aA3 = fma2(Ia[14], xq7.x, aA3);  aB3 = fma2(Ib[14], xq7.x, aB3);
        aA0 = fma2(Ia[15], xq7.y, aA0);  aB0 = fma2(Ib[15], xq7.y, aB0);
        u64 accA = add2(add2(aA0, aA1), add2(aA2, aA3));
        u64 accB = add2(add2(aB0, aB1), add2(aB2, aB3));

        // ---- input-coordinate output (warp1, off critical path) ----
        if (wid == 1 && lane < INPN) {
            float xv = *(const float*)(s_xd + (size_t)t * INPN + lane);  // low half
            X = fmaf(0.9f, X, xv);
            outb[(size_t)t * 20 + 4 + lane] = 0.1f * X;
        }

        __syncthreads();   // the only barrier per step

        // ---- cross-warp combine: 8 broadcast LDS.128 + exact int adds ----
        const int4* sp = &s_ipart[(t & 1) * 8];
        int4 v0 = sp[0], v1 = sp[1], v2 = sp[2], v3 = sp[3];
        int4 v4 = sp[4], v5 = sp[5], v6 = sp[6], v7 = sp[7];
        int U0 = ((v0.x + v1.x) + (v2.x + v3.x)) + ((v4.x + v5.x) + (v6.x + v7.x));
        int U1 = ((v0.y + v1.y) + (v2.y + v3.y)) + ((v4.y + v5.y) + (v6.y + v7.y));
        int U2 = ((v0.z + v1.z) + (v2.z + v3.z)) + ((v4.z + v5.z) + (v6.z + v7.z));
        int U3 = ((v0.w + v1.w) + (v2.w + v3.w)) + ((v4.w + v5.w) + (v6.w + v7.w));

        float uf0 = (float)U0, uf1 = (float)U1;   // S_Q * u_r
        float uf2 = (float)U2, uf3 = (float)U3;
        u64 U0d = pack2(uf0, uf0), U1d = pack2(uf1, uf1);
        u64 U2d = pack2(uf2, uf2), U3d = pack2(uf3, uf3);

        // h_{t+1} = acc + sum_r (a_s m_r / S_Q) * (S_Q u_r)
        u64 cA0 = fma2(mcA[1], U1d, mul2(mcA[0], U0d));
        u64 cB0 = fma2(mcB[1], U1d, mul2(mcB[0], U0d));
        u64 cA1 = fma2(mcA[3], U3d, mul2(mcA[2], U2d));
        u64 cB1 = fma2(mcB[3], U3d, mul2(mcB[2], U2d));
        hA = add2(accA, add2(cA0, cA1));
        hB = add2(accB, add2(cB0, cB1));

        // ---- low-rank coordinate output (warp0 lane0) ----
        if (wid == 0 && lane == 0) {
            S01 = fma2(c9, S01, pack2(uf0, uf1));
            S23 = fma2(c9, S23, pack2(uf2, uf3));
            float o0, o1, o2, o3;
            unpack2(mul2(asq, S01), o0, o1);
            unpack2(mul2(asq, S23), o2, o3);
            *(float4*)(outb + (size_t)t * 20) = make_float4(o0, o1, o2, o3);
        }
    }
}

extern "C" void kernel_launch(void* const* d_in, const int* in_sizes, int n_in,
                              void* d_out, int out_size) {
    const float* x = (const float*)d_in[0];
    const float* m = (const float*)d_in[1];
    const float* n = (const float*)d_in[2];
    const float* I = (const float*)d_in[3];
    cudaFuncSetAttribute(rnn_fused, cudaFuncAttributeMaxDynamicSharedMemorySize,
                         SMEM_TOTAL);
    rnn_fused<<<BATCH, NTHR, SMEM_TOTAL>>>(x, m, n, I, (float*)d_out);
}

// round 11
// speedup vs baseline: 1.7035x; 1.0024x over previous
#include <cuda_runtime.h>
#include <cstdint>

// MixtureLowRankRNN — GB300 sm_103a. Single fused kernel.
// Subspace identity: h_t ∈ colspan([m|I]) (h0=0) ⇒ outputs are basis coords:
//   y[:,t,0:4]  = a_s*S_{t+1},  S <- 0.9 S + u_t,  u_t = n^T tanh(h_t)
//   y[:,t,4:20] = 0.1*X_{t+1},  X <- 0.9 X + x_t
// Round 10: whole batch's x (64KB) staged pre-duplicated in 128KB dynamic
// smem at kernel start -> the 1024-step loop touches DRAM only for outputs.
// No Z scratch, no separate kernels. Int fixed-point redux reduction (S=2^21).

#define RANKN 4
#define INPN  16
#define TLEN  1024
#define BATCH 32
#define NTHR  256

#define S_Q   2097152.0f     // 2^21 fixed-point scale

typedef unsigned long long u64;

#define SMEM_X_BYTES  (TLEN * INPN * 8)          // duplicated pairs: 128 KB
#define SMEM_TOTAL    (SMEM_X_BYTES + 2 * 8 * 16)

__device__ __forceinline__ u64 pack2(float x, float y) {
    u64 r; asm("mov.b64 %0, {%1, %2};" : "=l"(r) : "f"(x), "f"(y)); return r;
}
__device__ __forceinline__ void unpack2(u64 v, float& x, float& y) {
    asm("mov.b64 {%0, %1}, %2;" : "=f"(x), "=f"(y) : "l"(v));
}
__device__ __forceinline__ u64 fma2(u64 a, u64 b, u64 c) {
    u64 d; asm("fma.rn.f32x2 %0, %1, %2, %3;" : "=l"(d) : "l"(a), "l"(b), "l"(c)); return d;
}
__device__ __forceinline__ u64 mul2(u64 a, u64 b) {
    u64 d; asm("mul.rn.f32x2 %0, %1, %2;" : "=l"(d) : "l"(a), "l"(b)); return d;
}
__device__ __forceinline__ u64 add2(u64 a, u64 b) {
    u64 d; asm("add.rn.f32x2 %0, %1, %2;" : "=l"(d) : "l"(a), "l"(b)); return d;
}
__device__ __forceinline__ float tanha(float x) {
    float r; asm("tanh.approx.f32 %0, %1;" : "=f"(r) : "f"(x)); return r;
}
__device__ __forceinline__ int redux_s32(int v) {
    int r; asm("redux.sync.add.s32 %0, %1, 0xffffffff;" : "=r"(r) : "r"(v)); return r;
}

__global__ __launch_bounds__(NTHR, 1)
void rnn_fused(const float* __restrict__ x,   // [B, T, 16]
               const float* __restrict__ m,   // [H, 4]
               const float* __restrict__ n,   // [H, 4]
               const float* __restrict__ I,   // [H, 16]
               float* __restrict__ out)       // [B, T, 20]
{
    extern __shared__ char smem[];
    u64*  s_xd    = (u64*)smem;                        // [TLEN*16] duplicated x
    int4* s_ipart = (int4*)(smem + SMEM_X_BYTES);      // [2][8]

    const int b    = blockIdx.x;
    const int tid  = threadIdx.x;
    const int wid  = tid >> 5;
    const int lane = tid & 31;

    const float a_s  = 0.1f * (500.0f / 1024.0f);
    const float invS = 1.0f / S_Q;

    // ---- stage the whole batch's x into smem, duplicated as f32x2 pairs ----
    const float* xb = x + (size_t)b * TLEN * INPN;
    {
        const float4* xr4 = (const float4*)xb;
        for (int idx = tid; idx < TLEN * INPN / 4; idx += NTHR) {
            float4 f = xr4[idx];
            s_xd[idx * 4 + 0] = pack2(f.x, f.x);
            s_xd[idx * 4 + 1] = pack2(f.y, f.y);
            s_xd[idx * 4 + 2] = pack2(f.z, f.z);
            s_xd[idx * 4 + 3] = pack2(f.w, f.w);
        }
    }

    // ---- weights in registers (pairs: A=(tid,tid+256), B=(tid+512,tid+768)) ----
    const int eA0 = tid,       eA1 = tid + 256;
    const int eB0 = tid + 512, eB1 = tid + 768;

    u64 naA[RANKN], naB[RANKN], mcA[RANKN], mcB[RANKN], Ia[INPN], Ib[INPN];
#pragma unroll
    for (int r = 0; r < RANKN; r++) {
        naA[r] = pack2(S_Q * n[eA0 * RANKN + r], S_Q * n[eA1 * RANKN + r]);
        naB[r] = pack2(S_Q * n[eB0 * RANKN + r], S_Q * n[eB1 * RANKN + r]);
        mcA[r] = pack2(a_s * invS * m[eA0 * RANKN + r], a_s * invS * m[eA1 * RANKN + r]);
        mcB[r] = pack2(a_s * invS * m[eB0 * RANKN + r], a_s * invS * m[eB1 * RANKN + r]);
    }
#pragma unroll
    for (int j = 0; j < INPN; j++) {
        Ia[j] = pack2(0.1f * I[eA0 * INPN + j], 0.1f * I[eA1 * INPN + j]);
        Ib[j] = pack2(0.1f * I[eB0 * INPN + j], 0.1f * I[eB1 * INPN + j]);
    }

    const u64 c9  = pack2(0.9f, 0.9f);
    const u64 asq = pack2(a_s * invS, a_s * invS);

    float* outb = out + (size_t)b * TLEN * 20;

    u64 hA = 0ull, hB = 0ull;
    u64 S01 = 0ull, S23 = 0ull;      // warp0 lane0, scaled domain
    float X = 0.f;                   // warp1 lanes 0..15

    __syncthreads();   // x staging complete

    for (int t = 0; t < TLEN; t++) {
        // ---- critical path: tanh(h), scaled low-rank dot, int redux ----
        float a0, a1, b0v, b1v;
        unpack2(hA, a0, a1); unpack2(hB, b0v, b1v);
        u64 thA = pack2(tanha(a0), tanha(a1));
        u64 thB = pack2(tanha(b0v), tanha(b1v));

        int pi[4];
#pragma unroll
        for (int r = 0; r < RANKN; r++) {
            float lo, hi; unpack2(fma2(naB[r], thB, mul2(naA[r], thA)), lo, hi);
            pi[r] = redux_s32(__float2int_rn(lo + hi));
        }
        if (lane == 0) s_ipart[(t & 1) * 8 + wid] = make_int4(pi[0], pi[1], pi[2], pi[3]);

        // ---- u-independent update from smem x: 8 LDS.128 + 4 parallel chains ----
        const ulonglong2* xp = (const ulonglong2*)(s_xd + (size_t)t * INPN);
        ulonglong2 xq0 = xp[0], xq1 = xp[1], xq2 = xp[2], xq3 = xp[3];
        u64 aA0 = fma2(c9, hA, mul2(Ia[0], xq0.x));
        u64 aB0 = fma2(c9, hB, mul2(Ib[0], xq0.x));
        u64 aA1 = fma2(Ia[2], xq1.x, mul2(Ia[1], xq0.y));
        u64 aB1 = fma2(Ib[2], xq1.x, mul2(Ib[1], xq0.y));
        u64 aA2 = fma2(Ia[4], xq2.x, mul2(Ia[3], xq1.y));
        u64 aB2 = fma2(Ib[4], xq2.x, mul2(Ib[3], xq1.y));
        u64 aA3 = fma2(Ia[6], xq3.x, mul2(Ia[5], xq2.y));
        u64 aB3 = fma2(Ib[6], xq3.x, mul2(Ib[5], xq2.y));
        ulonglong2 xq4 = xp[4], xq5 = xp[5], xq6 = xp[6], xq7 = xp[7];
        aA0 = fma2(Ia[7],  xq3.y, aA0);  aB0 = fma2(Ib[7],  xq3.y, aB0);
        aA1 = fma2(Ia[8],  xq4.x, aA1);  aB1 = fma2(Ib[8],  xq4.x, aB1);
        aA2 = fma2(Ia[9],  xq4.y, aA2);  aB2 = fma2(Ib[9],  xq4.y, aB2);
        aA3 = fma2(Ia[10], xq5.x, aA3);  aB3 = fma2(Ib[10], xq5.x, aB3);
        aA0 = fma2(Ia[11], xq5.y, aA0);  aB0 = fma2(Ib[11], xq5.y, aB0);
        aA1 = fma2(Ia[12], xq6.x, aA1);  aB1 = fma2(Ib[12], xq6.x, aB1);
        aA2 = fma2(Ia[13], xq6.y, aA2);  aB2 = fma2(Ib[13], xq6.y, aB2);
        aA3 = fma2(Ia[14], xq7.x, aA3);  aB3 = fma2(Ib[14], xq7.x, aB3);
        aA0 = fma2(Ia[15], xq7.y, aA0);  aB0 = fma2(Ib[15], xq7.y, aB0);
        u64 accA = add2(add2(aA0, aA1), add2(aA2, aA3));
        u64 accB = add2(add2(aB0, aB1), add2(aB2, aB3));

        // ---- input-coordinate output (warp1, off critical path) ----
        if (wid == 1 && lane < INPN) {
            float xv = *(const float*)(s_xd + (size_t)t * INPN + lane);  // low half
            X = fmaf(0.9f, X, xv);
            outb[(size_t)t * 20 + 4 + lane] = 0.1f * X;
        }

        __syncthreads();   // the only barrier per step

        // ---- cross-warp combine: 8 broadcast LDS.128 + exact int adds ----
        const int4* sp = &s_ipart[(t & 1) * 8];
        int4 v0 = sp[0], v1 = sp[1], v2 = sp[2], v3 = sp[3];
        int4 v4 = sp[4], v5 = sp[5], v6 = sp[6], v7 = sp[7];
        int U0 = ((v0.x + v1.x) + (v2.x + v3.x)) + ((v4.x + v5.x) + (v6.x + v7.x));
        int U1 = ((v0.y + v1.y) + (v2.y + v3.y)) + ((v4.y + v5.y) + (v6.y + v7.y));
        int U2 = ((v0.z + v1.z) + (v2.z + v3.z)) + ((v4.z + v5.z) + (v6.z + v7.z));
        int U3 = ((v0.w + v1.w) + (v2.w + v3.w)) + ((v4.w + v5.w) + (v6.w + v7.w));

        float uf0 = (float)U0, uf1 = (float)U1;   // S_Q * u_r
        float uf2 = (float)U2, uf3 = (float)U3;
        u64 U0d = pack2(uf0, uf0), U1d = pack2(uf1, uf1);
        u64 U2d = pack2(uf2, uf2), U3d = pack2(uf3, uf3);

        // h_{t+1} = acc + sum_r (a_s m_r / S_Q) * (S_Q u_r)
        u64 cA0 = fma2(mcA[1], U1d, mul2(mcA[0], U0d));
        u64 cB0 = fma2(mcB[1], U1d, mul2(mcB[0], U0d));
        u64 cA1 = fma2(mcA[3], U3d, mul2(mcA[2], U2d));
        u64 cB1 = fma2(mcB[3], U3d, mul2(mcB[2], U2d));
        hA = add2(accA, add2(cA0, cA1));
        hB = add2(accB, add2(cB0, cB1));

        // ---- low-rank coordinate output (warp0 lane0) ----
        if (wid == 0 && lane == 0) {
            S01 = fma2(c9, S01, pack2(uf0, uf1));
            S23 = fma2(c9, S23, pack2(uf2, uf3));
            float o0, o1, o2, o3;
            unpack2(mul2(asq, S01), o0, o1);
            unpack2(mul2(asq, S23), o2, o3);
            *(float4*)(outb + (size_t)t * 20) = make_float4(o0, o1, o2, o3);
        }
    }
}

extern "C" void kernel_launch(void* const* d_in, const int* in_sizes, int n_in,
                              void* d_out, int out_size) {
    const float* x = (const float*)d_in[0];
    const float* m = (const float*)d_in[1];
    const float* n = (const float*)d_in[2];
    const float* I = (const float*)d_in[3];
    cudaFuncSetAttribute(rnn_fused, cudaFuncAttributeMaxDynamicSharedMemorySize,
                         SMEM_TOTAL);
    rnn_fused<<<BATCH, NTHR, SMEM_TOTAL>>>(x, m, n, I, (float*)d_out);
}